// round 2
// baseline (speedup 1.0000x reference)
#include <cuda_runtime.h>

#define Hd 1024
#define Wd 1024
#define Bd 16

// Scratch: blurred grayscale field g [B,H,W], per-batch max(s) bits, gamma.
__device__ float d_g[(size_t)Bd * Hd * Wd];
__device__ unsigned int d_smax[Bd];
__device__ float d_gamma[Bd];

// Separable 1D Gaussian weights (outer(w,w) == gaussian_kernel(5,10)).
#define W0 0.19800304f
#define W1 0.20099548f
#define W2 0.20200297f

// ---------------------------------------------------------------------------
// jnp.gradient on a shared-memory tile: central interior, one-sided edges.
// (li,lj) is the local index of global (gi,gj); st is the smem row stride.
// ---------------------------------------------------------------------------
__device__ __forceinline__ float gHs(const float* s, int st, int li, int lj, int gi) {
    if (gi == 0)      return s[(li + 1) * st + lj] - s[li * st + lj];
    if (gi == Hd - 1) return s[li * st + lj] - s[(li - 1) * st + lj];
    return 0.5f * (s[(li + 1) * st + lj] - s[(li - 1) * st + lj]);
}
__device__ __forceinline__ float gWs(const float* s, int st, int li, int lj, int gj) {
    if (gj == 0)      return s[li * st + lj + 1] - s[li * st + lj];
    if (gj == Wd - 1) return s[li * st + lj] - s[li * st + lj - 1];
    return 0.5f * (s[li * st + lj + 1] - s[li * st + lj - 1]);
}
__device__ __forceinline__ void hess_s(const float* s, int st, int li, int lj,
                                       int gi, int gj,
                                       float& h00, float& h01, float& h11) {
    // h00 = grad_H(grad_H g)
    if (gi == 0)           h00 = gHs(s, st, li + 1, lj, 1) - gHs(s, st, li, lj, 0);
    else if (gi == Hd - 1) h00 = gHs(s, st, li, lj, Hd - 1) - gHs(s, st, li - 1, lj, Hd - 2);
    else                   h00 = 0.5f * (gHs(s, st, li + 1, lj, gi + 1) - gHs(s, st, li - 1, lj, gi - 1));
    // h01 = grad_W(grad_H g)
    if (gj == 0)           h01 = gHs(s, st, li, lj + 1, gi) - gHs(s, st, li, lj, gi);
    else if (gj == Wd - 1) h01 = gHs(s, st, li, lj, gi) - gHs(s, st, li, lj - 1, gi);
    else                   h01 = 0.5f * (gHs(s, st, li, lj + 1, gi) - gHs(s, st, li, lj - 1, gi));
    // h11 = grad_W(grad_W g)
    if (gj == 0)           h11 = gWs(s, st, li, lj + 1, 1) - gWs(s, st, li, lj, 0);
    else if (gj == Wd - 1) h11 = gWs(s, st, li, lj, Wd - 1) - gWs(s, st, li, lj - 1, Wd - 2);
    else                   h11 = 0.5f * (gWs(s, st, li, lj + 1, gj + 1) - gWs(s, st, li, lj - 1, gj - 1));
}

// ---------------------------------------------------------------------------
// K_init: reset per-batch max bits
// ---------------------------------------------------------------------------
__global__ void k_init() {
    if (threadIdx.x < Bd) d_smax[threadIdx.x] = 0u;
}

// ---------------------------------------------------------------------------
// K1: fused grayscale + separable 5x5 blur + s-max reduction.
// Tile 64x64 outputs, raw-gray halo 4 so g is valid with halo 2 in smem.
// 256 threads. smem: sgray[72][73] then overlay sg[68][69]; shb[72][69].
// ---------------------------------------------------------------------------
#define T1 64
#define SGY 73
#define SHB 69
#define SG  69

__global__ void __launch_bounds__(256) k_grayblur_smax(
        const float* __restrict__ x, const float* __restrict__ to_gray) {
    __shared__ float buf[72 * SGY + 72 * SHB];
    float* sgray = buf;                 // [72][SGY]
    float* shb   = buf + 72 * SGY;      // [72][SHB]
    float* sg    = buf;                 // [68][SG] overlays sgray

    const int b  = blockIdx.z;
    const int i0 = blockIdx.y * T1;
    const int j0 = blockIdx.x * T1;
    const int t  = threadIdx.x;

    const float c0 = to_gray[0], c1 = to_gray[1], c2 = to_gray[2];
    const float* __restrict__ xr = x + (size_t)b * 3 * Hd * Wd;
    const float* __restrict__ xg = xr + (size_t)Hd * Wd;
    const float* __restrict__ xb = xg + (size_t)Hd * Wd;

    // Load 72x72 gray tile (halo 4); zero outside image == SAME zero pad.
    for (int idx = t; idx < 72 * 72; idx += 256) {
        int li = idx / 72, lj = idx % 72;
        int gi = i0 + li - 4, gj = j0 + lj - 4;
        float v = 0.0f;
        if ((unsigned)gi < Hd && (unsigned)gj < Wd) {
            size_t o = (size_t)gi * Wd + gj;
            v = c0 * __ldg(xr + o) + c1 * __ldg(xg + o) + c2 * __ldg(xb + o);
        }
        sgray[li * SGY + lj] = v;
    }
    __syncthreads();

    // Horizontal 5-tap: 72 rows x 68 cols
    for (int idx = t; idx < 72 * 68; idx += 256) {
        int li = idx / 68, lj = idx % 68;
        const float* r = &sgray[li * SGY + lj];
        shb[li * SHB + lj] = W0 * (r[0] + r[4]) + W1 * (r[1] + r[3]) + W2 * r[2];
    }
    __syncthreads();

    // Vertical 5-tap: 68x68 g tile (halo 2), overlaying sgray (dead now).
    for (int idx = t; idx < 68 * 68; idx += 256) {
        int li = idx / 68, lj = idx % 68;
        float v = W0 * (shb[li * SHB + lj] + shb[(li + 4) * SHB + lj])
                + W1 * (shb[(li + 1) * SHB + lj] + shb[(li + 3) * SHB + lj])
                + W2 * shb[(li + 2) * SHB + lj];
        sg[li * SG + lj] = v;
    }
    __syncthreads();

    // Write interior g (coalesced, 64-wide rows)
    float* __restrict__ gout = d_g + (size_t)b * Hd * Wd;
    for (int idx = t; idx < T1 * T1; idx += 256) {
        int ii = idx >> 6, jj = idx & 63;
        gout[(size_t)(i0 + ii) * Wd + (j0 + jj)] = sg[(ii + 2) * SG + (jj + 2)];
    }

    // Compute s = ||eigvals|| over the tile, reduce to per-batch max.
    float m = 0.0f;
    for (int idx = t; idx < T1 * T1; idx += 256) {
        int ii = idx >> 6, jj = idx & 63;
        int gi = i0 + ii, gj = j0 + jj;
        float h00, h01, h11;
        hess_s(sg, SG, ii + 2, jj + 2, gi, gj, h00, h01, h11);
        float mean = 0.5f * (h00 + h11);
        float diff = 0.5f * (h00 - h11);
        float disc = sqrtf(diff * diff + h01 * h01);
        float e0 = mean - disc, e1 = mean + disc;
        m = fmaxf(m, sqrtf(e0 * e0 + e1 * e1));
    }
#pragma unroll
    for (int o = 16; o > 0; o >>= 1)
        m = fmaxf(m, __shfl_xor_sync(0xffffffffu, m, o));
    __shared__ float wm[8];
    int lane = t & 31, wid = t >> 5;
    if (lane == 0) wm[wid] = m;
    __syncthreads();
    if (wid == 0) {
        m = (lane < 8) ? wm[lane] : 0.0f;
#pragma unroll
        for (int o = 4; o > 0; o >>= 1)
            m = fmaxf(m, __shfl_xor_sync(0xffffffffu, m, o));
        if (lane == 0)
            atomicMax(&d_smax[b], __float_as_uint(m));  // s >= 0: bit order ok
    }
}

// ---------------------------------------------------------------------------
// K2: gamma = smax/2, with global all-zero -> 1.0 fallback
// ---------------------------------------------------------------------------
__global__ void k_gamma() {
    if (threadIdx.x == 0) {
        bool allz = true;
        for (int b = 0; b < Bd; b++)
            if (d_smax[b] != 0u) { allz = false; break; }
        for (int b = 0; b < Bd; b++)
            d_gamma[b] = allz ? 1.0f : 0.5f * __uint_as_float(d_smax[b]);
    }
}

// ---------------------------------------------------------------------------
// K3: final Frangi response; Hessian recomputed from a smem g tile.
// Tile 32 (H) x 128 (W), halo 2. 256 threads.
// ---------------------------------------------------------------------------
#define T4H 32
#define T4W 128
#define S4  133

__global__ void __launch_bounds__(256) k_final(float* __restrict__ out) {
    __shared__ float sg[(T4H + 4) * S4];

    const int b  = blockIdx.z;
    const int i0 = blockIdx.y * T4H;
    const int j0 = blockIdx.x * T4W;
    const int t  = threadIdx.x;
    const float* __restrict__ gp = d_g + (size_t)b * Hd * Wd;

    // Load (36 x 132) g tile, clamped (OOB values never read by edge formulas)
    for (int idx = t; idx < (T4H + 4) * (T4W + 4); idx += 256) {
        int li = idx / (T4W + 4), lj = idx % (T4W + 4);
        int gi = i0 + li - 2, gj = j0 + lj - 2;
        gi = gi < 0 ? 0 : (gi > Hd - 1 ? Hd - 1 : gi);
        gj = gj < 0 ? 0 : (gj > Wd - 1 ? Wd - 1 : gj);
        sg[li * S4 + lj] = __ldg(gp + (size_t)gi * Wd + gj);
    }
    __syncthreads();

    const float gm = d_gamma[b];
    const float inv2g2 = 1.0f / (2.0f * gm * gm);

    for (int idx = t; idx < T4H * T4W; idx += 256) {
        int ii = idx >> 7, jj = idx & 127;
        int gi = i0 + ii, gj = j0 + jj;
        float h00, h01, h11;
        hess_s(sg, S4, ii + 2, jj + 2, gi, gj, h00, h01, h11);

        float mean = 0.5f * (h00 + h11);
        float diff = 0.5f * (h00 - h11);
        float disc = sqrtf(diff * diff + h01 * h01);
        float e0 = mean - disc, e1 = mean + disc;

        bool swap = fabsf(e1) < fabsf(e0);
        float lam1 = swap ? e1 : e0;
        float lam2 = fmaxf(swap ? e0 : e1, 1e-10f);
        float r_b = fabsf(lam1) / lam2;
        float s2 = e0 * e0 + e1 * e1;

        float vals = expf(-2.0f * r_b * r_b) * (1.0f - expf(-s2 * inv2g2));
        float f = fmaxf(0.0f, vals);
        out[((size_t)b * Hd + gi) * Wd + gj] = (f <= 0.0f) ? 1.0f : f;
    }
}

// ---------------------------------------------------------------------------
extern "C" void kernel_launch(void* const* d_in, const int* in_sizes, int n_in,
                              void* d_out, int out_size) {
    const float* x  = (const float*)d_in[0];
    const float* tg = (const float*)d_in[1];
    if (n_in >= 2 && in_sizes[0] == 3) {  // defensive: order per metadata
        const float* tmp = x; x = tg; tg = tmp;
    }
    float* out = (float*)d_out;

    k_init<<<1, 32>>>();
    k_grayblur_smax<<<dim3(Wd / T1, Hd / T1, Bd), 256>>>(x, tg);
    k_gamma<<<1, 32>>>();
    k_final<<<dim3(Wd / T4W, Hd / T4H, Bd), 256>>>(out);
}

// round 4
// speedup vs baseline: 1.4228x; 1.4228x over previous
#include <cuda_runtime.h>

#define Hd 1024
#define Wd 1024
#define Bd 16

// Scratch: blurred grayscale g [B,H,W], per-batch max(s^2) bits, 1/(2*gamma^2).
__device__ float d_g[(size_t)Bd * Hd * Wd];
__device__ unsigned int d_smax2[Bd];
__device__ float d_inv2g2[Bd];

// Separable 1D Gaussian weights (outer(w,w) == gaussian_kernel(5,10)).
#define W0 0.19800304f
#define W1 0.20099548f
#define W2 0.20200297f

// ---------------------------------------------------------------------------
// Generic (border-correct) Hessian from a smem tile.
// jnp.gradient semantics: central interior, one-sided edges, applied twice.
// ---------------------------------------------------------------------------
__device__ __forceinline__ float gHs(const float* s, int st, int li, int lj, int gi) {
    if (gi == 0)      return s[(li + 1) * st + lj] - s[li * st + lj];
    if (gi == Hd - 1) return s[li * st + lj] - s[(li - 1) * st + lj];
    return 0.5f * (s[(li + 1) * st + lj] - s[(li - 1) * st + lj]);
}
__device__ __forceinline__ float gWs(const float* s, int st, int li, int lj, int gj) {
    if (gj == 0)      return s[li * st + lj + 1] - s[li * st + lj];
    if (gj == Wd - 1) return s[li * st + lj] - s[li * st + lj - 1];
    return 0.5f * (s[li * st + lj + 1] - s[li * st + lj - 1]);
}
__device__ __forceinline__ void hess_g(const float* s, int st, int li, int lj,
                                       int gi, int gj,
                                       float& h00, float& h01, float& h11) {
    if (gi == 0)           h00 = gHs(s, st, li + 1, lj, 1) - gHs(s, st, li, lj, 0);
    else if (gi == Hd - 1) h00 = gHs(s, st, li, lj, Hd - 1) - gHs(s, st, li - 1, lj, Hd - 2);
    else                   h00 = 0.5f * (gHs(s, st, li + 1, lj, gi + 1) - gHs(s, st, li - 1, lj, gi - 1));
    if (gj == 0)           h01 = gHs(s, st, li, lj + 1, gi) - gHs(s, st, li, lj, gi);
    else if (gj == Wd - 1) h01 = gHs(s, st, li, lj, gi) - gHs(s, st, li, lj - 1, gi);
    else                   h01 = 0.5f * (gHs(s, st, li, lj + 1, gi) - gHs(s, st, li, lj - 1, gi));
    if (gj == 0)           h11 = gWs(s, st, li, lj + 1, 1) - gWs(s, st, li, lj, 0);
    else if (gj == Wd - 1) h11 = gWs(s, st, li, lj, Wd - 1) - gWs(s, st, li, lj - 1, Wd - 2);
    else                   h11 = 0.5f * (gWs(s, st, li, lj + 1, gj + 1) - gWs(s, st, li, lj - 1, gj - 1));
}

__global__ void k_init() {
    if (threadIdx.x < Bd) d_smax2[threadIdx.x] = 0u;
}

// ---------------------------------------------------------------------------
// K1: grayscale + separable 5x5 blur + max(s^2) reduction.  Tile 64x64.
// sgray stride 76 (float4-aligned), shb stride 72, sg overlays sgray (stride 72).
// ---------------------------------------------------------------------------
#define SGS 76
#define SHS 72
#define SGT 72

template <bool CHECK>
__device__ __forceinline__ float s2_run(const float* sg, int lj, int r0,
                                        int i0, int gj, bool jb) {
    float m = 0.0f;
    const float* pc = sg + (r0 + 2) * SGT + lj;
    float cm2 = pc[-2 * SGT], cm1 = pc[-SGT], cc = pc[0], cp1 = pc[SGT], cp2 = pc[2 * SGT];
    float lm = pc[-SGT - 1], l0 = pc[-1], lp = pc[SGT - 1];
    float rm = pc[-SGT + 1], r0v = pc[1], rp = pc[SGT + 1];
#pragma unroll
    for (int k = 0; k < 16; k++) {
        float h00, h01, h11;
        if (CHECK) {
            int gi = i0 + r0 + k;
            if (jb | (gi < 2) | (gi >= Hd - 2)) {
                hess_g(sg, SGT, r0 + 2 + k, lj, gi, gj, h00, h01, h11);
            } else {
                h00 = 0.25f * (cp2 - 2.0f * cc + cm2);
                h01 = 0.25f * ((rp - rm) - (lp - lm));
                h11 = 0.25f * (pc[-2] - 2.0f * cc + pc[2]);
            }
        } else {
            h00 = 0.25f * (cp2 - 2.0f * cc + cm2);
            h01 = 0.25f * ((rp - rm) - (lp - lm));
            h11 = 0.25f * (pc[-2] - 2.0f * cc + pc[2]);
        }
        float mean = 0.5f * (h00 + h11);
        float diff = 0.5f * (h00 - h11);
        float s2 = 2.0f * (mean * mean + diff * diff + h01 * h01);
        m = fmaxf(m, s2);
        if (k < 15) {
            cm2 = cm1; cm1 = cc; cc = cp1; cp1 = cp2;
            lm = l0; l0 = lp; rm = r0v; r0v = rp;
            pc += SGT;
            cp2 = pc[2 * SGT];
            lp = pc[SGT - 1];
            rp = pc[SGT + 1];
        }
    }
    return m;
}

__global__ void __launch_bounds__(256) k_grayblur_smax(
        const float* __restrict__ x, const float* __restrict__ to_gray) {
    __shared__ float buf[72 * SGS + 72 * SHS];
    float* sgray = buf;              // [72][76]
    float* shb   = buf + 72 * SGS;   // [72][72], cols 0..67 used
    float* sg    = buf;              // [68][72] overlays sgray

    const int b  = blockIdx.z;
    const int i0 = blockIdx.y * 64;
    const int j0 = blockIdx.x * 64;
    const int t  = threadIdx.x;

    const float c0 = to_gray[0], c1 = to_gray[1], c2 = to_gray[2];
    const float* __restrict__ xr = x + (size_t)b * 3 * Hd * Wd;
    const float* __restrict__ xg = xr + (size_t)Hd * Wd;
    const float* __restrict__ xb = xg + (size_t)Hd * Wd;

    // Gray load: 72 rows x 18 float4-quads (quads are 4-aligned: all-in or all-out)
    for (int idx = t; idx < 72 * 18; idx += 256) {
        int li = idx / 18, q = idx - li * 18;
        int gi = i0 + li - 4, gjq = j0 + q * 4 - 4;
        float4 v = make_float4(0.f, 0.f, 0.f, 0.f);
        if ((unsigned)gi < Hd && (unsigned)gjq < Wd) {
            size_t o = (size_t)gi * Wd + gjq;
            float4 r = *(const float4*)(xr + o);
            float4 g = *(const float4*)(xg + o);
            float4 bb = *(const float4*)(xb + o);
            v.x = c0 * r.x + c1 * g.x + c2 * bb.x;
            v.y = c0 * r.y + c1 * g.y + c2 * bb.y;
            v.z = c0 * r.z + c1 * g.z + c2 * bb.z;
            v.w = c0 * r.w + c1 * g.w + c2 * bb.w;
        }
        *(float4*)&sgray[li * SGS + q * 4] = v;
    }
    __syncthreads();

    // Horizontal 5-tap: 72 rows x 17 quads (out cols 0..67)
    for (int idx = t; idx < 72 * 17; idx += 256) {
        int li = idx / 17, q = idx - li * 17;
        const float* r = &sgray[li * SGS + q * 4];
        float4 A = *(const float4*)r;
        float4 B = *(const float4*)(r + 4);
        float4 o;
        o.x = W0 * (A.x + B.x) + W1 * (A.y + A.w) + W2 * A.z;
        o.y = W0 * (A.y + B.y) + W1 * (A.z + B.x) + W2 * A.w;
        o.z = W0 * (A.z + B.z) + W1 * (A.w + B.y) + W2 * B.x;
        o.w = W0 * (A.w + B.w) + W1 * (B.x + B.z) + W2 * B.y;
        *(float4*)&shb[li * SHS + q * 4] = o;
    }
    __syncthreads();

    // Vertical 5-tap: 17 row-quads x 68 cols -> sg (overlays dead sgray)
    for (int idx = t; idx < 17 * 68; idx += 256) {
        int rq = idx / 68, lj = idx - rq * 68;
        const float* p = &shb[rq * 4 * SHS + lj];
        float a0 = p[0], a1 = p[SHS], a2 = p[2 * SHS], a3 = p[3 * SHS];
        float a4 = p[4 * SHS], a5 = p[5 * SHS], a6 = p[6 * SHS], a7 = p[7 * SHS];
        float* o = &sg[rq * 4 * SGT + lj];
        o[0]       = W0 * (a0 + a4) + W1 * (a1 + a3) + W2 * a2;
        o[SGT]     = W0 * (a1 + a5) + W1 * (a2 + a4) + W2 * a3;
        o[2 * SGT] = W0 * (a2 + a6) + W1 * (a3 + a5) + W2 * a4;
        o[3 * SGT] = W0 * (a3 + a7) + W1 * (a4 + a6) + W2 * a5;
    }
    __syncthreads();

    // Write interior g (float4, coalesced)
    float* __restrict__ gout = d_g + (size_t)b * Hd * Wd + (size_t)i0 * Wd + j0;
    for (int idx = t; idx < 1024; idx += 256) {
        int ii = idx >> 4, jq = (idx & 15) * 4;
        const float* p = &sg[(ii + 2) * SGT + jq + 2];
        float4 v; v.x = p[0]; v.y = p[1]; v.z = p[2]; v.w = p[3];
        *(float4*)&gout[(size_t)ii * Wd + jq] = v;
    }

    // max(s^2) over the 64x64 tile: thread (tx,ty) owns col tx, 16 rows.
    int tx = t & 63, ty = t >> 6;
    int gj = j0 + tx;
    bool jb = (gj < 2) | (gj >= Wd - 2);
    bool rowborder = (i0 == 0) | (i0 + 64 == Hd);
    float m;
    if (jb | rowborder)
        m = s2_run<true >(sg, tx + 2, ty * 16, i0, gj, jb);
    else
        m = s2_run<false>(sg, tx + 2, ty * 16, i0, gj, jb);

#pragma unroll
    for (int o = 16; o > 0; o >>= 1)
        m = fmaxf(m, __shfl_xor_sync(0xffffffffu, m, o));
    __shared__ float wm[8];
    int lane = t & 31, wid = t >> 5;
    if (lane == 0) wm[wid] = m;
    __syncthreads();
    if (wid == 0) {
        m = (lane < 8) ? wm[lane] : 0.0f;
#pragma unroll
        for (int o = 4; o > 0; o >>= 1)
            m = fmaxf(m, __shfl_xor_sync(0xffffffffu, m, o));
        if (lane == 0)
            atomicMax(&d_smax2[b], __float_as_uint(m));  // s2 >= 0
    }
}

// ---------------------------------------------------------------------------
// K2: inv2g2 = 1/(2*gamma^2), gamma = sqrt(smax2)/2, all-zero -> gamma 1
// ---------------------------------------------------------------------------
__global__ void k_gamma() {
    if (threadIdx.x == 0) {
        bool allz = true;
        for (int b = 0; b < Bd; b++)
            if (d_smax2[b] != 0u) { allz = false; break; }
        for (int b = 0; b < Bd; b++) {
            float gm = allz ? 1.0f : 0.5f * sqrtf(__uint_as_float(d_smax2[b]));
            d_inv2g2[b] = 1.0f / (2.0f * gm * gm);
        }
    }
}

// ---------------------------------------------------------------------------
// K3: final response. Tile 32H x 128W, stride 132. Thread owns col, 16 rows.
// ---------------------------------------------------------------------------
#define S3 132

template <bool CHECK>
__device__ __forceinline__ void fin_run(const float* sg, float* __restrict__ out,
                                        int b, int i0, int j0, int tx, int r0,
                                        bool jb, float inv2g2) {
    const int gj = j0 + tx;
    const int lj = tx + 2;
    const float* pc = sg + (r0 + 2) * S3 + lj;
    float cm2 = pc[-2 * S3], cm1 = pc[-S3], cc = pc[0], cp1 = pc[S3], cp2 = pc[2 * S3];
    float lm = pc[-S3 - 1], l0 = pc[-1], lp = pc[S3 - 1];
    float rm = pc[-S3 + 1], r0v = pc[1], rp = pc[S3 + 1];
    float* __restrict__ op = out + ((size_t)b * Hd + (i0 + r0)) * Wd + gj;
#pragma unroll
    for (int k = 0; k < 16; k++) {
        float h00, h01, h11;
        if (CHECK) {
            int gi = i0 + r0 + k;
            if (jb | (gi < 2) | (gi >= Hd - 2)) {
                hess_g(sg, S3, r0 + 2 + k, lj, gi, gj, h00, h01, h11);
            } else {
                h00 = 0.25f * (cp2 - 2.0f * cc + cm2);
                h01 = 0.25f * ((rp - rm) - (lp - lm));
                h11 = 0.25f * (pc[-2] - 2.0f * cc + pc[2]);
            }
        } else {
            h00 = 0.25f * (cp2 - 2.0f * cc + cm2);
            h01 = 0.25f * ((rp - rm) - (lp - lm));
            h11 = 0.25f * (pc[-2] - 2.0f * cc + pc[2]);
        }
        float mean = 0.5f * (h00 + h11);
        float diff = 0.5f * (h00 - h11);
        float d2 = diff * diff + h01 * h01;
        float disc = sqrtf(d2);
        float am = fabsf(mean);
        float lam2 = fmaxf(copysignf(am + disc, mean), 1e-10f);
        float lam1a = fabsf(am - disc);
        float rb = __fdividef(lam1a, lam2);
        float s2 = 2.0f * (mean * mean + d2);
        float vals = __expf(-2.0f * rb * rb) * (1.0f - __expf(-s2 * inv2g2));
        float f = fmaxf(0.0f, vals);
        *op = (f <= 0.0f) ? 1.0f : f;
        if (k < 15) {
            cm2 = cm1; cm1 = cc; cc = cp1; cp1 = cp2;
            lm = l0; l0 = lp; rm = r0v; r0v = rp;
            pc += S3;
            cp2 = pc[2 * S3];
            lp = pc[S3 - 1];
            rp = pc[S3 + 1];
            op += Wd;
        }
    }
}

__global__ void __launch_bounds__(256) k_final(float* __restrict__ out) {
    __shared__ float sg[36 * S3];

    const int b  = blockIdx.z;
    const int i0 = blockIdx.y * 32;
    const int j0 = blockIdx.x * 128;
    const int t  = threadIdx.x;
    const float* __restrict__ gp = d_g + (size_t)b * Hd * Wd;

    // Load 36x132 g tile (clamped; clamped values never read by edge formulas)
    for (int idx = t; idx < 36 * 132; idx += 256) {
        int li = idx / 132, lj = idx - li * 132;
        int gi = i0 + li - 2, gj = j0 + lj - 2;
        gi = gi < 0 ? 0 : (gi > Hd - 1 ? Hd - 1 : gi);
        gj = gj < 0 ? 0 : (gj > Wd - 1 ? Wd - 1 : gj);
        sg[li * S3 + lj] = __ldg(gp + (size_t)gi * Wd + gj);
    }
    __syncthreads();

    const float inv2g2 = d_inv2g2[b];
    int tx = t & 127, ty = t >> 7;
    int gj = j0 + tx;
    bool jb = (gj < 2) | (gj >= Wd - 2);
    bool rowborder = (i0 == 0) | (i0 + 32 == Hd);
    if (jb | rowborder)
        fin_run<true >(sg, out, b, i0, j0, tx, ty * 16, jb, inv2g2);
    else
        fin_run<false>(sg, out, b, i0, j0, tx, ty * 16, jb, inv2g2);
}

// ---------------------------------------------------------------------------
extern "C" void kernel_launch(void* const* d_in, const int* in_sizes, int n_in,
                              void* d_out, int out_size) {
    const float* x  = (const float*)d_in[0];
    const float* tg = (const float*)d_in[1];
    if (n_in >= 2 && in_sizes[0] == 3) {  // defensive: order per metadata
        const float* tmp = x; x = tg; tg = tmp;
    }
    float* out = (float*)d_out;

    k_init<<<1, 32>>>();
    k_grayblur_smax<<<dim3(Wd / 64, Hd / 64, Bd), 256>>>(x, tg);
    k_gamma<<<1, 32>>>();
    k_final<<<dim3(Wd / 128, Hd / 32, Bd), 256>>>(out);
}

// round 6
// speedup vs baseline: 1.7746x; 1.2473x over previous
#include <cuda_runtime.h>

#define Hd 1024
#define Wd 1024
#define Bd 16

// Scratch: per-pixel {t1 = exp(-2 rb^2), s2} interleaved; per-batch max(s^2).
__device__ float2 d_ts[(size_t)Bd * Hd * Wd];
__device__ unsigned int d_smax2[Bd];

// Separable 1D Gaussian weights (outer(w,w) == gaussian_kernel(5,10)).
#define W0 0.19800304f
#define W1 0.20099548f
#define W2 0.20200297f

// ---------------------------------------------------------------------------
// Generic (border-correct) Hessian from a smem tile.
// jnp.gradient semantics: central interior, one-sided edges, applied twice.
// ---------------------------------------------------------------------------
__device__ __forceinline__ float gHs(const float* s, int st, int li, int lj, int gi) {
    if (gi == 0)      return s[(li + 1) * st + lj] - s[li * st + lj];
    if (gi == Hd - 1) return s[li * st + lj] - s[(li - 1) * st + lj];
    return 0.5f * (s[(li + 1) * st + lj] - s[(li - 1) * st + lj]);
}
__device__ __forceinline__ float gWs(const float* s, int st, int li, int lj, int gj) {
    if (gj == 0)      return s[li * st + lj + 1] - s[li * st + lj];
    if (gj == Wd - 1) return s[li * st + lj] - s[li * st + lj - 1];
    return 0.5f * (s[li * st + lj + 1] - s[li * st + lj - 1]);
}
__device__ __forceinline__ void hess_g(const float* s, int st, int li, int lj,
                                       int gi, int gj,
                                       float& h00, float& h01, float& h11) {
    if (gi == 0)           h00 = gHs(s, st, li + 1, lj, 1) - gHs(s, st, li, lj, 0);
    else if (gi == Hd - 1) h00 = gHs(s, st, li, lj, Hd - 1) - gHs(s, st, li - 1, lj, Hd - 2);
    else                   h00 = 0.5f * (gHs(s, st, li + 1, lj, gi + 1) - gHs(s, st, li - 1, lj, gi - 1));
    if (gj == 0)           h01 = gHs(s, st, li, lj + 1, gi) - gHs(s, st, li, lj, gi);
    else if (gj == Wd - 1) h01 = gHs(s, st, li, lj, gi) - gHs(s, st, li, lj - 1, gi);
    else                   h01 = 0.5f * (gHs(s, st, li, lj + 1, gi) - gHs(s, st, li, lj - 1, gi));
    if (gj == 0)           h11 = gWs(s, st, li, lj + 1, 1) - gWs(s, st, li, lj, 0);
    else if (gj == Wd - 1) h11 = gWs(s, st, li, lj, Wd - 1) - gWs(s, st, li, lj - 1, Wd - 2);
    else                   h11 = 0.5f * (gWs(s, st, li, lj + 1, gj + 1) - gWs(s, st, li, lj - 1, gj - 1));
}

__global__ void k_init() {
    if (threadIdx.x < Bd) d_smax2[threadIdx.x] = 0u;
}

// ---------------------------------------------------------------------------
// K1: grayscale + separable 5x5 blur + Hessian -> {t1, s2} + max(s^2).
// Tile 64x64. sgray stride 76 (float4-aligned), shb stride 72, sg overlays
// sgray (stride 72, interior at [2..65][2..65]).
// ---------------------------------------------------------------------------
#define SGS 76
#define SHS 72
#define SGT 72

template <bool CHECK>
__device__ __forceinline__ float ts_run(const float* sg, float2* __restrict__ tsp,
                                        int lj, int r0, int i0, int gj, bool jb) {
    float m = 0.0f;
    const float* pc = sg + (r0 + 2) * SGT + lj;
    float cm2 = pc[-2 * SGT], cm1 = pc[-SGT], cc = pc[0], cp1 = pc[SGT], cp2 = pc[2 * SGT];
    float lm = pc[-SGT - 1], l0 = pc[-1], lp = pc[SGT - 1];
    float rm = pc[-SGT + 1], r0v = pc[1], rp = pc[SGT + 1];
#pragma unroll
    for (int k = 0; k < 16; k++) {
        float h00, h01, h11;
        if (CHECK) {
            int gi = i0 + r0 + k;
            if (jb | (gi < 2) | (gi >= Hd - 2)) {
                hess_g(sg, SGT, r0 + 2 + k, lj, gi, gj, h00, h01, h11);
            } else {
                h00 = 0.25f * (cp2 - 2.0f * cc + cm2);
                h01 = 0.25f * ((rp - rm) - (lp - lm));
                h11 = 0.25f * (pc[-2] - 2.0f * cc + pc[2]);
            }
        } else {
            h00 = 0.25f * (cp2 - 2.0f * cc + cm2);
            h01 = 0.25f * ((rp - rm) - (lp - lm));
            h11 = 0.25f * (pc[-2] - 2.0f * cc + pc[2]);
        }
        float mean = 0.5f * (h00 + h11);
        float diff = 0.5f * (h00 - h11);
        float d2 = diff * diff + h01 * h01;
        float disc = sqrtf(d2);
        float am = fabsf(mean);
        float lam2 = fmaxf(copysignf(am + disc, mean), 1e-10f);
        float lam1a = fabsf(am - disc);
        float rb = __fdividef(lam1a, lam2);
        float s2 = 2.0f * (mean * mean + d2);
        float t1 = __expf(-2.0f * rb * rb);
        *tsp = make_float2(t1, s2);
        m = fmaxf(m, s2);
        if (k < 15) {
            cm2 = cm1; cm1 = cc; cc = cp1; cp1 = cp2;
            lm = l0; l0 = lp; rm = r0v; r0v = rp;
            pc += SGT;
            cp2 = pc[2 * SGT];
            lp = pc[SGT - 1];
            rp = pc[SGT + 1];
            tsp += Wd;
        }
    }
    return m;
}

__global__ void __launch_bounds__(256) k_grayblur_ts(
        const float* __restrict__ x, const float* __restrict__ to_gray) {
    __shared__ float buf[72 * SGS + 72 * SHS];
    float* sgray = buf;              // [72][76]
    float* shb   = buf + 72 * SGS;   // [72][72], cols 0..67 used
    float* sg    = buf;              // [68][72] overlays sgray

    const int b  = blockIdx.z;
    const int i0 = blockIdx.y * 64;
    const int j0 = blockIdx.x * 64;
    const int t  = threadIdx.x;

    const float c0 = to_gray[0], c1 = to_gray[1], c2 = to_gray[2];
    const float* __restrict__ xr = x + (size_t)b * 3 * Hd * Wd;
    const float* __restrict__ xg = xr + (size_t)Hd * Wd;
    const float* __restrict__ xb = xg + (size_t)Hd * Wd;

    // Gray load: 72 rows x 18 float4-quads (halo 4). Interior blocks skip checks.
    const bool interior = (blockIdx.x > 0) & (blockIdx.x < gridDim.x - 1) &
                          (blockIdx.y > 0) & (blockIdx.y < gridDim.y - 1);
    if (interior) {
        for (int idx = t; idx < 72 * 18; idx += 256) {
            int li = idx / 18, q = idx - li * 18;
            size_t o = (size_t)(i0 + li - 4) * Wd + (j0 + q * 4 - 4);
            float4 r = *(const float4*)(xr + o);
            float4 g = *(const float4*)(xg + o);
            float4 bb = *(const float4*)(xb + o);
            float4 v;
            v.x = c0 * r.x + c1 * g.x + c2 * bb.x;
            v.y = c0 * r.y + c1 * g.y + c2 * bb.y;
            v.z = c0 * r.z + c1 * g.z + c2 * bb.z;
            v.w = c0 * r.w + c1 * g.w + c2 * bb.w;
            *(float4*)&sgray[li * SGS + q * 4] = v;
        }
    } else {
        for (int idx = t; idx < 72 * 18; idx += 256) {
            int li = idx / 18, q = idx - li * 18;
            int gi = i0 + li - 4, gjq = j0 + q * 4 - 4;
            float4 v = make_float4(0.f, 0.f, 0.f, 0.f);
            if ((unsigned)gi < Hd && (unsigned)gjq < Wd) {
                size_t o = (size_t)gi * Wd + gjq;
                float4 r = *(const float4*)(xr + o);
                float4 g = *(const float4*)(xg + o);
                float4 bb = *(const float4*)(xb + o);
                v.x = c0 * r.x + c1 * g.x + c2 * bb.x;
                v.y = c0 * r.y + c1 * g.y + c2 * bb.y;
                v.z = c0 * r.z + c1 * g.z + c2 * bb.z;
                v.w = c0 * r.w + c1 * g.w + c2 * bb.w;
            }
            *(float4*)&sgray[li * SGS + q * 4] = v;
        }
    }
    __syncthreads();

    // Horizontal 5-tap: 72 rows x 17 quads (out cols 0..67)
    for (int idx = t; idx < 72 * 17; idx += 256) {
        int li = idx / 17, q = idx - li * 17;
        const float* r = &sgray[li * SGS + q * 4];
        float4 A = *(const float4*)r;
        float4 B = *(const float4*)(r + 4);
        float4 o;
        o.x = W0 * (A.x + B.x) + W1 * (A.y + A.w) + W2 * A.z;
        o.y = W0 * (A.y + B.y) + W1 * (A.z + B.x) + W2 * A.w;
        o.z = W0 * (A.z + B.z) + W1 * (A.w + B.y) + W2 * B.x;
        o.w = W0 * (A.w + B.w) + W1 * (B.x + B.z) + W2 * B.y;
        *(float4*)&shb[li * SHS + q * 4] = o;
    }
    __syncthreads();

    // Vertical 5-tap: 17 row-quads x 68 cols -> sg (overlays dead sgray)
    for (int idx = t; idx < 17 * 68; idx += 256) {
        int rq = idx / 68, lj = idx - rq * 68;
        const float* p = &shb[rq * 4 * SHS + lj];
        float a0 = p[0], a1 = p[SHS], a2 = p[2 * SHS], a3 = p[3 * SHS];
        float a4 = p[4 * SHS], a5 = p[5 * SHS], a6 = p[6 * SHS], a7 = p[7 * SHS];
        float* o = &sg[rq * 4 * SGT + lj];
        o[0]       = W0 * (a0 + a4) + W1 * (a1 + a3) + W2 * a2;
        o[SGT]     = W0 * (a1 + a5) + W1 * (a2 + a4) + W2 * a3;
        o[2 * SGT] = W0 * (a2 + a6) + W1 * (a3 + a5) + W2 * a4;
        o[3 * SGT] = W0 * (a3 + a7) + W1 * (a4 + a6) + W2 * a5;
    }
    __syncthreads();

    // Hessian -> {t1, s2} + max(s2): thread (tx,ty) owns col tx, 16 rows.
    int tx = t & 63, ty = t >> 6;
    int gj = j0 + tx;
    float2* tsp = d_ts + ((size_t)b * Hd + (i0 + ty * 16)) * Wd + gj;
    bool jb = (gj < 2) | (gj >= Wd - 2);
    bool rowborder = (i0 == 0) | (i0 + 64 == Hd);
    float m;
    if (jb | rowborder)
        m = ts_run<true >(sg, tsp, tx + 2, ty * 16, i0, gj, jb);
    else
        m = ts_run<false>(sg, tsp, tx + 2, ty * 16, i0, gj, jb);

#pragma unroll
    for (int o = 16; o > 0; o >>= 1)
        m = fmaxf(m, __shfl_xor_sync(0xffffffffu, m, o));
    __shared__ float wm[8];
    int lane = t & 31, wid = t >> 5;
    if (lane == 0) wm[wid] = m;
    __syncthreads();
    if (wid == 0) {
        m = (lane < 8) ? wm[lane] : 0.0f;
#pragma unroll
        for (int o = 4; o > 0; o >>= 1)
            m = fmaxf(m, __shfl_xor_sync(0xffffffffu, m, o));
        if (lane == 0)
            atomicMax(&d_smax2[b], __float_as_uint(m));  // s2 >= 0
    }
}

// ---------------------------------------------------------------------------
// K2: final elementwise response. 1 float4 output (4 px) per thread.
// gamma derived in-block from d_smax2 (fold of old k_gamma).
// ---------------------------------------------------------------------------
__device__ __forceinline__ float fin1(float t1, float s2, float inv) {
    float vals = t1 * (1.0f - __expf(-s2 * inv));
    float f = fmaxf(0.0f, vals);
    return (f <= 0.0f) ? 1.0f : f;
}

__global__ void __launch_bounds__(256) k_final(float* __restrict__ out) {
    __shared__ float sinv;
    if (threadIdx.x == 0) {
        unsigned int orall = 0u;
#pragma unroll
        for (int i = 0; i < Bd; i++) orall |= d_smax2[i];
        int b = blockIdx.x >> 10;  // 1024 blocks per image (1M px / 1024 px-blk)
        float gm = (orall == 0u) ? 1.0f : 0.5f * sqrtf(__uint_as_float(d_smax2[b]));
        sinv = 1.0f / (2.0f * gm * gm);
    }
    __syncthreads();
    const float inv = sinv;

    size_t i4 = (size_t)blockIdx.x * 256 + threadIdx.x;   // float4-output index
    const float4* tp = (const float4*)d_ts + i4 * 2;
    float4 a = tp[0];   // {t1_0, s2_0, t1_1, s2_1}
    float4 c = tp[1];   // {t1_2, s2_2, t1_3, s2_3}
    float4 o;
    o.x = fin1(a.x, a.y, inv);
    o.y = fin1(a.z, a.w, inv);
    o.z = fin1(c.x, c.y, inv);
    o.w = fin1(c.z, c.w, inv);
    ((float4*)out)[i4] = o;
}

// ---------------------------------------------------------------------------
extern "C" void kernel_launch(void* const* d_in, const int* in_sizes, int n_in,
                              void* d_out, int out_size) {
    const float* x  = (const float*)d_in[0];
    const float* tg = (const float*)d_in[1];
    if (n_in >= 2 && in_sizes[0] == 3) {  // defensive: order per metadata
        const float* tmp = x; x = tg; tg = tmp;
    }
    float* out = (float*)d_out;

    k_init<<<1, 32>>>();
    k_grayblur_ts<<<dim3(Wd / 64, Hd / 64, Bd), 256>>>(x, tg);
    k_final<<<(Bd * Hd * Wd) / (256 * 4), 256>>>(out);
}

// round 8
// speedup vs baseline: 1.9746x; 1.1127x over previous
#include <cuda_runtime.h>
#include <cuda_fp16.h>

#define Hd 1024
#define Wd 1024
#define Bd 16

// Scratch: per-pixel packed {t1 = exp(-2 rb^2), s2} as half2 (4B/px);
// per-block s2 maxima; completion counter; per-batch 1/(2*gamma^2).
__device__ __half2 d_ts[(size_t)Bd * Hd * Wd];
__device__ float d_blockmax[Bd * 256];
__device__ unsigned int d_counter = 0;
__device__ float d_inv2g2[Bd];

// Separable 1D Gaussian weights (outer(w,w) == gaussian_kernel(5,10)).
#define W0 0.19800304f
#define W1 0.20099548f
#define W2 0.20200297f

// ---------------------------------------------------------------------------
// Generic (border-correct) Hessian from a smem tile.
// jnp.gradient semantics: central interior, one-sided edges, applied twice.
// ---------------------------------------------------------------------------
__device__ __forceinline__ float gHs(const float* s, int st, int li, int lj, int gi) {
    if (gi == 0)      return s[(li + 1) * st + lj] - s[li * st + lj];
    if (gi == Hd - 1) return s[li * st + lj] - s[(li - 1) * st + lj];
    return 0.5f * (s[(li + 1) * st + lj] - s[(li - 1) * st + lj]);
}
__device__ __forceinline__ float gWs(const float* s, int st, int li, int lj, int gj) {
    if (gj == 0)      return s[li * st + lj + 1] - s[li * st + lj];
    if (gj == Wd - 1) return s[li * st + lj] - s[li * st + lj - 1];
    return 0.5f * (s[li * st + lj + 1] - s[li * st + lj - 1]);
}
__device__ __forceinline__ void hess_g(const float* s, int st, int li, int lj,
                                       int gi, int gj,
                                       float& h00, float& h01, float& h11) {
    if (gi == 0)           h00 = gHs(s, st, li + 1, lj, 1) - gHs(s, st, li, lj, 0);
    else if (gi == Hd - 1) h00 = gHs(s, st, li, lj, Hd - 1) - gHs(s, st, li - 1, lj, Hd - 2);
    else                   h00 = 0.5f * (gHs(s, st, li + 1, lj, gi + 1) - gHs(s, st, li - 1, lj, gi - 1));
    if (gj == 0)           h01 = gHs(s, st, li, lj + 1, gi) - gHs(s, st, li, lj, gi);
    else if (gj == Wd - 1) h01 = gHs(s, st, li, lj, gi) - gHs(s, st, li, lj - 1, gi);
    else                   h01 = 0.5f * (gHs(s, st, li, lj + 1, gi) - gHs(s, st, li, lj - 1, gi));
    if (gj == 0)           h11 = gWs(s, st, li, lj + 1, 1) - gWs(s, st, li, lj, 0);
    else if (gj == Wd - 1) h11 = gWs(s, st, li, lj, Wd - 1) - gWs(s, st, li, lj - 1, Wd - 2);
    else                   h11 = 0.5f * (gWs(s, st, li, lj + 1, gj + 1) - gWs(s, st, li, lj - 1, gj - 1));
}

// ---------------------------------------------------------------------------
// K1: grayscale + separable 5x5 blur + Hessian -> packed {t1, s2} + max(s^2).
// Tile 64x64. sgray stride 76 (float4-aligned), shb stride 72, sg overlays
// sgray (stride 72, interior at [2..65][2..65]).
// Last-finishing block reduces per-block maxima into d_inv2g2 (self-reset
// counter keeps graph replays deterministic).
// ---------------------------------------------------------------------------
#define SGS 76
#define SHS 72
#define SGT 72

template <bool CHECK>
__device__ __forceinline__ float ts_run(const float* sg, __half2* __restrict__ tsp,
                                        int lj, int r0, int i0, int gj, bool jb) {
    float m = 0.0f;
    const float* pc = sg + (r0 + 2) * SGT + lj;
    float cm2 = pc[-2 * SGT], cm1 = pc[-SGT], cc = pc[0], cp1 = pc[SGT], cp2 = pc[2 * SGT];
    float lm = pc[-SGT - 1], l0 = pc[-1], lp = pc[SGT - 1];
    float rm = pc[-SGT + 1], r0v = pc[1], rp = pc[SGT + 1];
#pragma unroll
    for (int k = 0; k < 16; k++) {
        float h00, h01, h11;
        if (CHECK) {
            int gi = i0 + r0 + k;
            if (jb | (gi < 2) | (gi >= Hd - 2)) {
                hess_g(sg, SGT, r0 + 2 + k, lj, gi, gj, h00, h01, h11);
            } else {
                h00 = 0.25f * (cp2 - 2.0f * cc + cm2);
                h01 = 0.25f * ((rp - rm) - (lp - lm));
                h11 = 0.25f * (pc[-2] - 2.0f * cc + pc[2]);
            }
        } else {
            h00 = 0.25f * (cp2 - 2.0f * cc + cm2);
            h01 = 0.25f * ((rp - rm) - (lp - lm));
            h11 = 0.25f * (pc[-2] - 2.0f * cc + pc[2]);
        }
        float mean = 0.5f * (h00 + h11);
        float diff = 0.5f * (h00 - h11);
        float d2 = diff * diff + h01 * h01;
        float disc = sqrtf(d2);
        float am = fabsf(mean);
        float lam2 = fmaxf(copysignf(am + disc, mean), 1e-10f);
        float lam1a = fabsf(am - disc);
        float rb = __fdividef(lam1a, lam2);
        float s2 = 2.0f * (mean * mean + d2);
        float t1 = __expf(-2.0f * rb * rb);
        *tsp = __floats2half2_rn(t1, s2);
        m = fmaxf(m, s2);
        if (k < 15) {
            cm2 = cm1; cm1 = cc; cc = cp1; cp1 = cp2;
            lm = l0; l0 = lp; rm = r0v; r0v = rp;
            pc += SGT;
            cp2 = pc[2 * SGT];
            lp = pc[SGT - 1];
            rp = pc[SGT + 1];
            tsp += Wd;
        }
    }
    return m;
}

__global__ void __launch_bounds__(256) k_grayblur_ts(
        const float* __restrict__ x, const float* __restrict__ to_gray) {
    __shared__ float buf[72 * SGS + 72 * SHS];
    float* sgray = buf;              // [72][76]
    float* shb   = buf + 72 * SGS;   // [72][72], cols 0..67 used
    float* sg    = buf;              // [68][72] overlays sgray

    const int b  = blockIdx.z;
    const int i0 = blockIdx.y * 64;
    const int j0 = blockIdx.x * 64;
    const int t  = threadIdx.x;

    const float c0 = to_gray[0], c1 = to_gray[1], c2 = to_gray[2];
    const float* __restrict__ xr = x + (size_t)b * 3 * Hd * Wd;
    const float* __restrict__ xg = xr + (size_t)Hd * Wd;
    const float* __restrict__ xb = xg + (size_t)Hd * Wd;

    // Gray load: 72 rows x 18 float4-quads (halo 4). Interior blocks skip checks.
    const bool interior = (blockIdx.x > 0) & (blockIdx.x < gridDim.x - 1) &
                          (blockIdx.y > 0) & (blockIdx.y < gridDim.y - 1);
    if (interior) {
        for (int idx = t; idx < 72 * 18; idx += 256) {
            int li = idx / 18, q = idx - li * 18;
            size_t o = (size_t)(i0 + li - 4) * Wd + (j0 + q * 4 - 4);
            float4 r = *(const float4*)(xr + o);
            float4 g = *(const float4*)(xg + o);
            float4 bb = *(const float4*)(xb + o);
            float4 v;
            v.x = c0 * r.x + c1 * g.x + c2 * bb.x;
            v.y = c0 * r.y + c1 * g.y + c2 * bb.y;
            v.z = c0 * r.z + c1 * g.z + c2 * bb.z;
            v.w = c0 * r.w + c1 * g.w + c2 * bb.w;
            *(float4*)&sgray[li * SGS + q * 4] = v;
        }
    } else {
        for (int idx = t; idx < 72 * 18; idx += 256) {
            int li = idx / 18, q = idx - li * 18;
            int gi = i0 + li - 4, gjq = j0 + q * 4 - 4;
            float4 v = make_float4(0.f, 0.f, 0.f, 0.f);
            if ((unsigned)gi < Hd && (unsigned)gjq < Wd) {
                size_t o = (size_t)gi * Wd + gjq;
                float4 r = *(const float4*)(xr + o);
                float4 g = *(const float4*)(xg + o);
                float4 bb = *(const float4*)(xb + o);
                v.x = c0 * r.x + c1 * g.x + c2 * bb.x;
                v.y = c0 * r.y + c1 * g.y + c2 * bb.y;
                v.z = c0 * r.z + c1 * g.z + c2 * bb.z;
                v.w = c0 * r.w + c1 * g.w + c2 * bb.w;
            }
            *(float4*)&sgray[li * SGS + q * 4] = v;
        }
    }
    __syncthreads();

    // Horizontal 5-tap: 72 rows x 17 quads (out cols 0..67)
    for (int idx = t; idx < 72 * 17; idx += 256) {
        int li = idx / 17, q = idx - li * 17;
        const float* r = &sgray[li * SGS + q * 4];
        float4 A = *(const float4*)r;
        float4 B = *(const float4*)(r + 4);
        float4 o;
        o.x = W0 * (A.x + B.x) + W1 * (A.y + A.w) + W2 * A.z;
        o.y = W0 * (A.y + B.y) + W1 * (A.z + B.x) + W2 * A.w;
        o.z = W0 * (A.z + B.z) + W1 * (A.w + B.y) + W2 * B.x;
        o.w = W0 * (A.w + B.w) + W1 * (B.x + B.z) + W2 * B.y;
        *(float4*)&shb[li * SHS + q * 4] = o;
    }
    __syncthreads();

    // Vertical 5-tap: 17 row-quads x 68 cols -> sg (overlays dead sgray)
    for (int idx = t; idx < 17 * 68; idx += 256) {
        int rq = idx / 68, lj = idx - rq * 68;
        const float* p = &shb[rq * 4 * SHS + lj];
        float a0 = p[0], a1 = p[SHS], a2 = p[2 * SHS], a3 = p[3 * SHS];
        float a4 = p[4 * SHS], a5 = p[5 * SHS], a6 = p[6 * SHS], a7 = p[7 * SHS];
        float* o = &sg[rq * 4 * SGT + lj];
        o[0]       = W0 * (a0 + a4) + W1 * (a1 + a3) + W2 * a2;
        o[SGT]     = W0 * (a1 + a5) + W1 * (a2 + a4) + W2 * a3;
        o[2 * SGT] = W0 * (a2 + a6) + W1 * (a3 + a5) + W2 * a4;
        o[3 * SGT] = W0 * (a3 + a7) + W1 * (a4 + a6) + W2 * a5;
    }
    __syncthreads();

    // Hessian -> packed {t1, s2} + max(s2): thread (tx,ty) owns col tx, 16 rows.
    int tx = t & 63, ty = t >> 6;
    int gj = j0 + tx;
    __half2* tsp = d_ts + ((size_t)b * Hd + (i0 + ty * 16)) * Wd + gj;
    bool jb = (gj < 2) | (gj >= Wd - 2);
    bool rowborder = (i0 == 0) | (i0 + 64 == Hd);
    float m;
    if (jb | rowborder)
        m = ts_run<true >(sg, tsp, tx + 2, ty * 16, i0, gj, jb);
    else
        m = ts_run<false>(sg, tsp, tx + 2, ty * 16, i0, gj, jb);

#pragma unroll
    for (int o = 16; o > 0; o >>= 1)
        m = fmaxf(m, __shfl_xor_sync(0xffffffffu, m, o));
    __shared__ float wm[8];
    __shared__ int sflag;
    int lane = t & 31, wid = t >> 5;
    if (lane == 0) wm[wid] = m;
    __syncthreads();
    if (t == 0) {
        m = wm[0];
#pragma unroll
        for (int i = 1; i < 8; i++) m = fmaxf(m, wm[i]);
        // plain store: every slot rewritten every run -> no reset kernel needed
        d_blockmax[(b << 8) | (blockIdx.y << 4) | blockIdx.x] = m;
        __threadfence();
        unsigned int c = atomicAdd(&d_counter, 1u);
        sflag = (c == (unsigned)(Bd * 256 - 1));
    }
    __syncthreads();

    if (sflag) {  // block-uniform: last-finishing block computes gamma
        __shared__ float sbm[Bd];
#pragma unroll
        for (int rep = 0; rep < 2; rep++) {
            int bb = wid * 2 + rep;
            float m2 = 0.0f;
            for (int i = lane; i < 256; i += 32)
                m2 = fmaxf(m2, d_blockmax[(bb << 8) | i]);
#pragma unroll
            for (int o = 16; o > 0; o >>= 1)
                m2 = fmaxf(m2, __shfl_xor_sync(0xffffffffu, m2, o));
            if (lane == 0) sbm[bb] = m2;
        }
        __syncthreads();
        if (t == 0) {
            float orall = 0.0f;
#pragma unroll
            for (int i = 0; i < Bd; i++) orall = fmaxf(orall, sbm[i]);
#pragma unroll
            for (int i = 0; i < Bd; i++) {
                float gm = (orall == 0.0f) ? 1.0f : 0.5f * sqrtf(sbm[i]);
                d_inv2g2[i] = 1.0f / (2.0f * gm * gm);
            }
            d_counter = 0;  // self-reset: deterministic across graph replays
        }
    }
}

// ---------------------------------------------------------------------------
// K2: final elementwise response. One uint4 = 4 half2 = 4 px per thread.
// ---------------------------------------------------------------------------
__device__ __forceinline__ float fin1(float t1, float s2, float inv) {
    float vals = t1 * (1.0f - __expf(-s2 * inv));
    float f = fmaxf(0.0f, vals);
    return (f <= 0.0f) ? 1.0f : f;
}

__global__ void __launch_bounds__(256) k_final(float* __restrict__ out) {
    const size_t i4 = (size_t)blockIdx.x * 256 + threadIdx.x;  // 4-px group
    const float inv = d_inv2g2[blockIdx.x >> 10];  // 1024 blocks per image

    uint4 raw = ((const uint4*)d_ts)[i4];
    float2 p0 = __half22float2(*reinterpret_cast<const __half2*>(&raw.x));
    float2 p1 = __half22float2(*reinterpret_cast<const __half2*>(&raw.y));
    float2 p2 = __half22float2(*reinterpret_cast<const __half2*>(&raw.z));
    float2 p3 = __half22float2(*reinterpret_cast<const __half2*>(&raw.w));
    float4 o;
    o.x = fin1(p0.x, p0.y, inv);
    o.y = fin1(p1.x, p1.y, inv);
    o.z = fin1(p2.x, p2.y, inv);
    o.w = fin1(p3.x, p3.y, inv);
    ((float4*)out)[i4] = o;
}

// ---------------------------------------------------------------------------
extern "C" void kernel_launch(void* const* d_in, const int* in_sizes, int n_in,
                              void* d_out, int out_size) {
    const float* x  = (const float*)d_in[0];
    const float* tg = (const float*)d_in[1];
    if (n_in >= 2 && in_sizes[0] == 3) {  // defensive: order per metadata
        const float* tmp = x; x = tg; tg = tmp;
    }
    float* out = (float*)d_out;

    k_grayblur_ts<<<dim3(Wd / 64, Hd / 64, Bd), 256>>>(x, tg);
    k_final<<<(Bd * Hd * Wd) / (256 * 4), 256>>>(out);
}

// round 10
// speedup vs baseline: 1.9806x; 1.0030x over previous
#include <cuda_runtime.h>
#include <cuda_fp16.h>

#define Hd 1024
#define Wd 1024
#define Bd 16

// Scratch: per-pixel packed {t1 = exp(-2 rb^2), s2} as half2 (4B/px);
// per-block s2 maxima; completion counter; per-batch 1/(2*gamma^2).
__device__ __half2 d_ts[(size_t)Bd * Hd * Wd];
__device__ float d_blockmax[Bd * 256];
__device__ unsigned int d_counter = 0;
__device__ float d_inv2g2[Bd];

// Separable 1D Gaussian weights (outer(w,w) == gaussian_kernel(5,10)).
#define W0 0.19800304f
#define W1 0.20099548f
#define W2 0.20200297f

// ---------------------------------------------------------------------------
// Packed f32x2 helpers (Blackwell sm_103a). Lane0 = .x (even col), lane1 = .y.
// ---------------------------------------------------------------------------
typedef unsigned long long u64t;
__device__ __forceinline__ u64t pk2(float lo, float hi) {
    u64t r; asm("mov.b64 %0,{%1,%2};" : "=l"(r) : "f"(lo), "f"(hi)); return r;
}
__device__ __forceinline__ void upk2(u64t v, float& lo, float& hi) {
    asm("mov.b64 {%0,%1},%2;" : "=f"(lo), "=f"(hi) : "l"(v));
}
__device__ __forceinline__ u64t add2(u64t a, u64t b) {
    u64t r; asm("add.rn.f32x2 %0,%1,%2;" : "=l"(r) : "l"(a), "l"(b)); return r;
}
__device__ __forceinline__ u64t mul2(u64t a, u64t b) {
    u64t r; asm("mul.rn.f32x2 %0,%1,%2;" : "=l"(r) : "l"(a), "l"(b)); return r;
}
__device__ __forceinline__ u64t fma2(u64t a, u64t b, u64t c) {
    u64t r; asm("fma.rn.f32x2 %0,%1,%2,%3;" : "=l"(r) : "l"(a), "l"(b), "l"(c)); return r;
}

// ---------------------------------------------------------------------------
// Generic (border-correct) Hessian from a smem tile.
// jnp.gradient semantics: central interior, one-sided edges, applied twice.
// ---------------------------------------------------------------------------
__device__ __forceinline__ float gHs(const float* s, int st, int li, int lj, int gi) {
    if (gi == 0)      return s[(li + 1) * st + lj] - s[li * st + lj];
    if (gi == Hd - 1) return s[li * st + lj] - s[(li - 1) * st + lj];
    return 0.5f * (s[(li + 1) * st + lj] - s[(li - 1) * st + lj]);
}
__device__ __forceinline__ float gWs(const float* s, int st, int li, int lj, int gj) {
    if (gj == 0)      return s[li * st + lj + 1] - s[li * st + lj];
    if (gj == Wd - 1) return s[li * st + lj] - s[li * st + lj - 1];
    return 0.5f * (s[li * st + lj + 1] - s[li * st + lj - 1]);
}
__device__ __forceinline__ void hess_g(const float* s, int st, int li, int lj,
                                       int gi, int gj,
                                       float& h00, float& h01, float& h11) {
    if (gi == 0)           h00 = gHs(s, st, li + 1, lj, 1) - gHs(s, st, li, lj, 0);
    else if (gi == Hd - 1) h00 = gHs(s, st, li, lj, Hd - 1) - gHs(s, st, li - 1, lj, Hd - 2);
    else                   h00 = 0.5f * (gHs(s, st, li + 1, lj, gi + 1) - gHs(s, st, li - 1, lj, gi - 1));
    if (gj == 0)           h01 = gHs(s, st, li, lj + 1, gi) - gHs(s, st, li, lj, gi);
    else if (gj == Wd - 1) h01 = gHs(s, st, li, lj, gi) - gHs(s, st, li, lj - 1, gi);
    else                   h01 = 0.5f * (gHs(s, st, li, lj + 1, gi) - gHs(s, st, li, lj - 1, gi));
    if (gj == 0)           h11 = gWs(s, st, li, lj + 1, 1) - gWs(s, st, li, lj, 0);
    else if (gj == Wd - 1) h11 = gWs(s, st, li, lj, Wd - 1) - gWs(s, st, li, lj - 1, Wd - 2);
    else                   h11 = 0.5f * (gWs(s, st, li, lj + 1, gj + 1) - gWs(s, st, li, lj - 1, gj - 1));
}

__device__ __forceinline__ float eig_store(float mean, float d2, float s2,
                                           __half2* tsp) {
    float disc = sqrtf(d2);
    float am = fabsf(mean);
    float lam2 = fmaxf(copysignf(am + disc, mean), 1e-10f);
    float lam1a = fabsf(am - disc);
    float rb = __fdividef(lam1a, lam2);
    float t1 = __expf(-2.0f * rb * rb);
    *tsp = __floats2half2_rn(t1, s2);
    return s2;
}

// ---------------------------------------------------------------------------
// K1: grayscale + separable 5x5 blur + Hessian -> packed {t1, s2} + max(s^2).
// Tile 64x64. sgray stride 76, shb stride 72, sg overlays sgray (stride 72,
// interior at [2..65][2..65]).
// ---------------------------------------------------------------------------
#define SGS 76
#define SHS 72
#define SGT 72

// Interior pair path: thread owns cols (2*txp, 2*txp+1), 8 rows starting r0.
// cq = txp: w[d][0]={2txp,2txp+1}, w[d][1]={lj0,lj0+1}(=center, lj0=2txp+2),
// w[d][2]={2txp+4,2txp+5}.
__device__ __forceinline__ float ts_pair_run(const float* sg, __half2* tsp,
                                             int cq, int r0) {
    const float2* s2p_base = (const float2*)sg;  // sg 16B-aligned, SGT/2=36
    float m = 0.0f;
    float2 w[5][3];
#pragma unroll
    for (int d = 0; d < 5; d++) {
#pragma unroll
        for (int c = 0; c < 3; c++)
            w[d][c] = s2p_base[(size_t)(r0 + d) * (SGT / 2) + cq + c];
    }
    const u64t kM1 = pk2(-1.0f, -1.0f);
    const u64t kM2 = pk2(-2.0f, -2.0f);
    const u64t k18 = pk2(0.125f, 0.125f);
    const u64t k14 = pk2(0.25f, 0.25f);
    const u64t kTwo = pk2(2.0f, 2.0f);
#pragma unroll
    for (int k = 0; k < 8; k++) {
        // packed operands (lane0 = px at lj0, lane1 = px at lj0+1)
        u64t c_m2 = *(const u64t*)&w[0][1];
        u64t c_0  = *(const u64t*)&w[2][1];
        u64t c_p2 = *(const u64t*)&w[4][1];
        u64t l_0  = *(const u64t*)&w[2][0];
        u64t r_0  = *(const u64t*)&w[2][2];
        // H00 = c_m2 + c_p2 - 2*c_0   (= 4*h00)
        u64t H00 = fma2(c_0, kM2, add2(c_m2, c_p2));
        // H11: lane0 = w[2][0].x + w[2][2].x - 2*w[2][1].x etc. (= 4*h11)
        u64t H11 = fma2(c_0, kM2, add2(l_0, r_0));
        // H01 = (R3-L3)-(R1-L1); R_r={w[r][1].y,w[r][2].x}, L_r={w[r][0].y,w[r][1].x}
        u64t R1 = pk2(w[1][1].y, w[1][2].x);
        u64t L1 = pk2(w[1][0].y, w[1][1].x);
        u64t R3 = pk2(w[3][1].y, w[3][2].x);
        u64t L3 = pk2(w[3][0].y, w[3][1].x);
        u64t D3 = fma2(L3, kM1, R3);
        u64t D1 = fma2(L1, kM1, R1);
        u64t H01 = fma2(D1, kM1, D3);
        // mean = 0.125*(H00+H11); diff = 0.125*(H00-H11); h01 = 0.25*H01
        u64t meanp = mul2(add2(H00, H11), k18);
        u64t diffp = mul2(fma2(H11, kM1, H00), k18);
        u64t h01p  = mul2(H01, k14);
        // d2 = diff^2 + h01^2 ; s2 = 2*(mean^2 + d2)
        u64t d2p = fma2(diffp, diffp, mul2(h01p, h01p));
        u64t s2p = mul2(fma2(meanp, meanp, d2p), kTwo);

        float ma, mb, da, db, sa, sb;
        upk2(meanp, ma, mb);
        upk2(d2p, da, db);
        upk2(s2p, sa, sb);
        __half2 ha, hb;
        {   // scalar eigen tail (MUFU-bound anyway)
            float disc = sqrtf(da);
            float am = fabsf(ma);
            float lam2v = fmaxf(copysignf(am + disc, ma), 1e-10f);
            float rb = __fdividef(fabsf(am - disc), lam2v);
            ha = __floats2half2_rn(__expf(-2.0f * rb * rb), sa);
        }
        {
            float disc = sqrtf(db);
            float am = fabsf(mb);
            float lam2v = fmaxf(copysignf(am + disc, mb), 1e-10f);
            float rb = __fdividef(fabsf(am - disc), lam2v);
            hb = __floats2half2_rn(__expf(-2.0f * rb * rb), sb);
        }
        *(uint2*)tsp = make_uint2(*(unsigned int*)&ha, *(unsigned int*)&hb);
        m = fmaxf(m, fmaxf(sa, sb));
        tsp += Wd;  // one image row (Wd half2 per row)
        if (k < 7) {
#pragma unroll
            for (int d = 0; d < 4; d++) {
                w[d][0] = w[d + 1][0]; w[d][1] = w[d + 1][1]; w[d][2] = w[d + 1][2];
            }
#pragma unroll
            for (int c = 0; c < 3; c++)
                w[4][c] = s2p_base[(size_t)(r0 + k + 5) * (SGT / 2) + cq + c];
        }
    }
    return m;
}

// Border path: fully scalar, per-pixel generic/interior selection (rare).
__device__ __forceinline__ float ts_border_run(const float* sg, __half2* tsp0,
                                               int txp, int r0, int i0, int j0) {
    float m = 0.0f;
#pragma unroll
    for (int c = 0; c < 2; c++) {
        int lj = 2 * txp + c + 2;
        int gj = j0 + 2 * txp + c;
        __half2* tsp = tsp0 + c;
        for (int k = 0; k < 8; k++) {
            int gi = i0 + r0 + k;
            int li = r0 + k + 2;
            float h00, h01, h11;
            if ((gj < 2) | (gj >= Wd - 2) | (gi < 2) | (gi >= Hd - 2)) {
                hess_g(sg, SGT, li, lj, gi, gj, h00, h01, h11);
            } else {
                const float* pc = sg + li * SGT + lj;
                h00 = 0.25f * (pc[2 * SGT] - 2.0f * pc[0] + pc[-2 * SGT]);
                h01 = 0.25f * ((pc[SGT + 1] - pc[-SGT + 1]) - (pc[SGT - 1] - pc[-SGT - 1]));
                h11 = 0.25f * (pc[-2] - 2.0f * pc[0] + pc[2]);
            }
            float mean = 0.5f * (h00 + h11);
            float diff = 0.5f * (h00 - h11);
            float d2 = diff * diff + h01 * h01;
            float s2 = 2.0f * (mean * mean + d2);
            m = fmaxf(m, eig_store(mean, d2, s2, tsp));
            tsp += Wd;
        }
    }
    return m;
}

__global__ void __launch_bounds__(256) k_grayblur_ts(
        const float* __restrict__ x, const float* __restrict__ to_gray) {
    __shared__ __align__(16) float buf[72 * SGS + 72 * SHS];
    float* sgray = buf;              // [72][76]
    float* shb   = buf + 72 * SGS;   // [72][72], cols 0..67 used
    float* sg    = buf;              // [68][72] overlays sgray

    const int b  = blockIdx.z;
    const int i0 = blockIdx.y * 64;
    const int j0 = blockIdx.x * 64;
    const int t  = threadIdx.x;

    const float c0 = to_gray[0], c1 = to_gray[1], c2 = to_gray[2];
    const float* __restrict__ xr = x + (size_t)b * 3 * Hd * Wd;
    const float* __restrict__ xg = xr + (size_t)Hd * Wd;
    const float* __restrict__ xb = xg + (size_t)Hd * Wd;

    // Gray load: 72 rows x 18 float4-quads (halo 4). Interior blocks skip checks.
    const bool interior = (blockIdx.x > 0) & (blockIdx.x < gridDim.x - 1) &
                          (blockIdx.y > 0) & (blockIdx.y < gridDim.y - 1);
    if (interior) {
        for (int idx = t; idx < 72 * 18; idx += 256) {
            int li = idx / 18, q = idx - li * 18;
            size_t o = (size_t)(i0 + li - 4) * Wd + (j0 + q * 4 - 4);
            float4 r = *(const float4*)(xr + o);
            float4 g = *(const float4*)(xg + o);
            float4 bb = *(const float4*)(xb + o);
            float4 v;
            v.x = c0 * r.x + c1 * g.x + c2 * bb.x;
            v.y = c0 * r.y + c1 * g.y + c2 * bb.y;
            v.z = c0 * r.z + c1 * g.z + c2 * bb.z;
            v.w = c0 * r.w + c1 * g.w + c2 * bb.w;
            *(float4*)&sgray[li * SGS + q * 4] = v;
        }
    } else {
        for (int idx = t; idx < 72 * 18; idx += 256) {
            int li = idx / 18, q = idx - li * 18;
            int gi = i0 + li - 4, gjq = j0 + q * 4 - 4;
            float4 v = make_float4(0.f, 0.f, 0.f, 0.f);
            if ((unsigned)gi < Hd && (unsigned)gjq < Wd) {
                size_t o = (size_t)gi * Wd + gjq;
                float4 r = *(const float4*)(xr + o);
                float4 g = *(const float4*)(xg + o);
                float4 bb = *(const float4*)(xb + o);
                v.x = c0 * r.x + c1 * g.x + c2 * bb.x;
                v.y = c0 * r.y + c1 * g.y + c2 * bb.y;
                v.z = c0 * r.z + c1 * g.z + c2 * bb.z;
                v.w = c0 * r.w + c1 * g.w + c2 * bb.w;
            }
            *(float4*)&sgray[li * SGS + q * 4] = v;
        }
    }
    __syncthreads();

    // Horizontal 5-tap: 72 rows x 17 quads (out cols 0..67)
    for (int idx = t; idx < 72 * 17; idx += 256) {
        int li = idx / 17, q = idx - li * 17;
        const float* r = &sgray[li * SGS + q * 4];
        float4 A = *(const float4*)r;
        float4 B = *(const float4*)(r + 4);
        float4 o;
        o.x = W0 * (A.x + B.x) + W1 * (A.y + A.w) + W2 * A.z;
        o.y = W0 * (A.y + B.y) + W1 * (A.z + B.x) + W2 * A.w;
        o.z = W0 * (A.z + B.z) + W1 * (A.w + B.y) + W2 * B.x;
        o.w = W0 * (A.w + B.w) + W1 * (B.x + B.z) + W2 * B.y;
        *(float4*)&shb[li * SHS + q * 4] = o;
    }
    __syncthreads();

    // Vertical 5-tap: 17 row-quads x 68 cols -> sg (overlays dead sgray)
    for (int idx = t; idx < 17 * 68; idx += 256) {
        int rq = idx / 68, lj = idx - rq * 68;
        const float* p = &shb[rq * 4 * SHS + lj];
        float a0 = p[0], a1 = p[SHS], a2 = p[2 * SHS], a3 = p[3 * SHS];
        float a4 = p[4 * SHS], a5 = p[5 * SHS], a6 = p[6 * SHS], a7 = p[7 * SHS];
        float* o = &sg[rq * 4 * SGT + lj];
        o[0]       = W0 * (a0 + a4) + W1 * (a1 + a3) + W2 * a2;
        o[SGT]     = W0 * (a1 + a5) + W1 * (a2 + a4) + W2 * a3;
        o[2 * SGT] = W0 * (a2 + a6) + W1 * (a3 + a5) + W2 * a4;
        o[3 * SGT] = W0 * (a3 + a7) + W1 * (a4 + a6) + W2 * a5;
    }
    __syncthreads();

    // Hessian -> packed {t1, s2} + max(s2): thread owns col-pair txp, 8 rows.
    int txp = t & 31, ty = t >> 5;
    int r0 = ty * 8;
    int gj0 = j0 + 2 * txp;
    __half2* tsp = d_ts + ((size_t)b * Hd + (i0 + r0)) * Wd + gj0;
    bool jb = (gj0 < 2) | (gj0 + 1 >= Wd - 2);
    bool rowborder = (i0 == 0) | (i0 + 64 == Hd);
    float m;
    if (jb | rowborder)
        m = ts_border_run(sg, tsp, txp, r0, i0, j0);
    else
        m = ts_pair_run(sg, tsp, txp, r0);  // cq = txp (center = cq+1)

#pragma unroll
    for (int o = 16; o > 0; o >>= 1)
        m = fmaxf(m, __shfl_xor_sync(0xffffffffu, m, o));
    __shared__ float wm[8];
    __shared__ int sflag;
    int lane = t & 31, wid = t >> 5;
    if (lane == 0) wm[wid] = m;
    __syncthreads();
    if (t == 0) {
        m = wm[0];
#pragma unroll
        for (int i = 1; i < 8; i++) m = fmaxf(m, wm[i]);
        d_blockmax[(b << 8) | (blockIdx.y << 4) | blockIdx.x] = m;
        __threadfence();
        unsigned int c = atomicAdd(&d_counter, 1u);
        sflag = (c == (unsigned)(Bd * 256 - 1));
    }
    __syncthreads();

    if (sflag) {  // last-finishing block computes gamma (self-reset counter)
        __shared__ float sbm[Bd];
#pragma unroll
        for (int rep = 0; rep < 2; rep++) {
            int bb = wid * 2 + rep;
            float m2 = 0.0f;
            for (int i = lane; i < 256; i += 32)
                m2 = fmaxf(m2, d_blockmax[(bb << 8) | i]);
#pragma unroll
            for (int o = 16; o > 0; o >>= 1)
                m2 = fmaxf(m2, __shfl_xor_sync(0xffffffffu, m2, o));
            if (lane == 0) sbm[bb] = m2;
        }
        __syncthreads();
        if (t == 0) {
            float orall = 0.0f;
#pragma unroll
            for (int i = 0; i < Bd; i++) orall = fmaxf(orall, sbm[i]);
#pragma unroll
            for (int i = 0; i < Bd; i++) {
                float gm = (orall == 0.0f) ? 1.0f : 0.5f * sqrtf(sbm[i]);
                d_inv2g2[i] = 1.0f / (2.0f * gm * gm);
            }
            d_counter = 0;  // deterministic across graph replays
        }
    }
}

// ---------------------------------------------------------------------------
// K2: final elementwise response. One uint4 = 4 half2 = 4 px per thread.
// Reversed block order: reads d_ts tail-first (freshest in L2 from k1).
// ---------------------------------------------------------------------------
__device__ __forceinline__ float fin1(float t1, float s2, float inv) {
    float vals = t1 * (1.0f - __expf(-s2 * inv));
    float f = fmaxf(0.0f, vals);
    return (f <= 0.0f) ? 1.0f : f;
}

__global__ void __launch_bounds__(256) k_final(float* __restrict__ out) {
    const unsigned bi = gridDim.x - 1 - blockIdx.x;           // reversed order
    const size_t i4 = (size_t)bi * 256 + threadIdx.x;         // 4-px group
    const float inv = d_inv2g2[bi >> 10];                     // 1024 blk/image

    uint4 raw = ((const uint4*)d_ts)[i4];
    float2 p0 = __half22float2(*reinterpret_cast<const __half2*>(&raw.x));
    float2 p1 = __half22float2(*reinterpret_cast<const __half2*>(&raw.y));
    float2 p2 = __half22float2(*reinterpret_cast<const __half2*>(&raw.z));
    float2 p3 = __half22float2(*reinterpret_cast<const __half2*>(&raw.w));
    float4 o;
    o.x = fin1(p0.x, p0.y, inv);
    o.y = fin1(p1.x, p1.y, inv);
    o.z = fin1(p2.x, p2.y, inv);
    o.w = fin1(p3.x, p3.y, inv);
    ((float4*)out)[i4] = o;
}

// ---------------------------------------------------------------------------
extern "C" void kernel_launch(void* const* d_in, const int* in_sizes, int n_in,
                              void* d_out, int out_size) {
    const float* x  = (const float*)d_in[0];
    const float* tg = (const float*)d_in[1];
    if (n_in >= 2 && in_sizes[0] == 3) {  // defensive: order per metadata
        const float* tmp = x; x = tg; tg = tmp;
    }
    float* out = (float*)d_out;

    k_grayblur_ts<<<dim3(Wd / 64, Hd / 64, Bd), 256>>>(x, tg);
    k_final<<<(Bd * Hd * Wd) / (256 * 4), 256>>>(out);
}

// round 11
// speedup vs baseline: 2.2659x; 1.1441x over previous
#include <cuda_runtime.h>
#include <cuda_fp16.h>

#define Hd 1024
#define Wd 1024
#define Bd 16

// Scratch: per-pixel packed {t1 = exp(-2 rb^2), s2} as half2 (4B/px);
// per-block s2 maxima; completion counter; per-batch 1/(2*gamma^2).
__device__ __half2 d_ts[(size_t)Bd * Hd * Wd];
__device__ float d_blockmax[Bd * 128];
__device__ unsigned int d_counter = 0;
__device__ float d_inv2g2[Bd];

// Separable 1D Gaussian weights (outer(w,w) == gaussian_kernel(5,10)).
#define W0 0.19800304f
#define W1 0.20099548f
#define W2 0.20200297f

// Tile geometry: 128 wide x 64 tall, halo 4.
#define SGS 136   // sgray stride (floats), 72 rows
#define SHS 132   // shb stride, 72 rows (cols 0..131)
#define SGT 132   // sg stride, 68 rows (overlays sgray)
#define SGT2 66   // sg stride in float2

// ---------------------------------------------------------------------------
// Packed f32x2 helpers (sm_103a). Lane0 = .x (even col), lane1 = .y.
// ---------------------------------------------------------------------------
typedef unsigned long long u64t;
__device__ __forceinline__ u64t pk2(float lo, float hi) {
    u64t r; asm("mov.b64 %0,{%1,%2};" : "=l"(r) : "f"(lo), "f"(hi)); return r;
}
__device__ __forceinline__ void upk2(u64t v, float& lo, float& hi) {
    asm("mov.b64 {%0,%1},%2;" : "=f"(lo), "=f"(hi) : "l"(v));
}
__device__ __forceinline__ u64t add2(u64t a, u64t b) {
    u64t r; asm("add.rn.f32x2 %0,%1,%2;" : "=l"(r) : "l"(a), "l"(b)); return r;
}
__device__ __forceinline__ u64t mul2(u64t a, u64t b) {
    u64t r; asm("mul.rn.f32x2 %0,%1,%2;" : "=l"(r) : "l"(a), "l"(b)); return r;
}
__device__ __forceinline__ u64t fma2(u64t a, u64t b, u64t c) {
    u64t r; asm("fma.rn.f32x2 %0,%1,%2,%3;" : "=l"(r) : "l"(a), "l"(b), "l"(c)); return r;
}

// ---------------------------------------------------------------------------
// Generic (border-correct) Hessian from a smem tile.
// jnp.gradient semantics: central interior, one-sided edges, applied twice.
// ---------------------------------------------------------------------------
__device__ __forceinline__ float gHs(const float* s, int st, int li, int lj, int gi) {
    if (gi == 0)      return s[(li + 1) * st + lj] - s[li * st + lj];
    if (gi == Hd - 1) return s[li * st + lj] - s[(li - 1) * st + lj];
    return 0.5f * (s[(li + 1) * st + lj] - s[(li - 1) * st + lj]);
}
__device__ __forceinline__ float gWs(const float* s, int st, int li, int lj, int gj) {
    if (gj == 0)      return s[li * st + lj + 1] - s[li * st + lj];
    if (gj == Wd - 1) return s[li * st + lj] - s[li * st + lj - 1];
    return 0.5f * (s[li * st + lj + 1] - s[li * st + lj - 1]);
}
__device__ __forceinline__ void hess_g(const float* s, int st, int li, int lj,
                                       int gi, int gj,
                                       float& h00, float& h01, float& h11) {
    if (gi == 0)           h00 = gHs(s, st, li + 1, lj, 1) - gHs(s, st, li, lj, 0);
    else if (gi == Hd - 1) h00 = gHs(s, st, li, lj, Hd - 1) - gHs(s, st, li - 1, lj, Hd - 2);
    else                   h00 = 0.5f * (gHs(s, st, li + 1, lj, gi + 1) - gHs(s, st, li - 1, lj, gi - 1));
    if (gj == 0)           h01 = gHs(s, st, li, lj + 1, gi) - gHs(s, st, li, lj, gi);
    else if (gj == Wd - 1) h01 = gHs(s, st, li, lj, gi) - gHs(s, st, li, lj - 1, gi);
    else                   h01 = 0.5f * (gHs(s, st, li, lj + 1, gi) - gHs(s, st, li, lj - 1, gi));
    if (gj == 0)           h11 = gWs(s, st, li, lj + 1, 1) - gWs(s, st, li, lj, 0);
    else if (gj == Wd - 1) h11 = gWs(s, st, li, lj, Wd - 1) - gWs(s, st, li, lj - 1, Wd - 2);
    else                   h11 = 0.5f * (gWs(s, st, li, lj + 1, gj + 1) - gWs(s, st, li, lj - 1, gj - 1));
}

__device__ __forceinline__ float eig_store(float mean, float d2, float s2,
                                           __half2* tsp) {
    float disc = sqrtf(d2);
    float am = fabsf(mean);
    float lam2 = fmaxf(copysignf(am + disc, mean), 1e-10f);
    float lam1a = fabsf(am - disc);
    float rb = __fdividef(lam1a, lam2);
    float t1 = __expf(-2.0f * rb * rb);
    *tsp = __floats2half2_rn(t1, s2);
    return s2;
}

// ---------------------------------------------------------------------------
// Interior pair path: thread owns cols (2*txp, 2*txp+1), 8 rows from r0.
// cq = txp: w[d][1] = center pair {lj0, lj0+1}, lj0 = 2*txp + 2.
// ---------------------------------------------------------------------------
__device__ __forceinline__ float ts_pair_run(const float* sg, __half2* tsp,
                                             int cq, int r0) {
    const float2* s2p_base = (const float2*)sg;  // sg 16B-aligned
    float m = 0.0f;
    float2 w[5][3];
#pragma unroll
    for (int d = 0; d < 5; d++) {
#pragma unroll
        for (int c = 0; c < 3; c++)
            w[d][c] = s2p_base[(size_t)(r0 + d) * SGT2 + cq + c];
    }
    const u64t kM1 = pk2(-1.0f, -1.0f);
    const u64t kM2 = pk2(-2.0f, -2.0f);
    const u64t k18 = pk2(0.125f, 0.125f);
    const u64t k14 = pk2(0.25f, 0.25f);
    const u64t kTwo = pk2(2.0f, 2.0f);
#pragma unroll
    for (int k = 0; k < 8; k++) {
        u64t c_m2 = *(const u64t*)&w[0][1];
        u64t c_0  = *(const u64t*)&w[2][1];
        u64t c_p2 = *(const u64t*)&w[4][1];
        u64t l_0  = *(const u64t*)&w[2][0];
        u64t r_0  = *(const u64t*)&w[2][2];
        u64t H00 = fma2(c_0, kM2, add2(c_m2, c_p2));          // 4*h00
        u64t H11 = fma2(c_0, kM2, add2(l_0, r_0));            // 4*h11
        u64t R1 = pk2(w[1][1].y, w[1][2].x);
        u64t L1 = pk2(w[1][0].y, w[1][1].x);
        u64t R3 = pk2(w[3][1].y, w[3][2].x);
        u64t L3 = pk2(w[3][0].y, w[3][1].x);
        u64t D3 = fma2(L3, kM1, R3);
        u64t D1 = fma2(L1, kM1, R1);
        u64t H01 = fma2(D1, kM1, D3);                          // 4*h01
        u64t meanp = mul2(add2(H00, H11), k18);
        u64t diffp = mul2(fma2(H11, kM1, H00), k18);
        u64t h01p  = mul2(H01, k14);
        u64t d2p = fma2(diffp, diffp, mul2(h01p, h01p));
        u64t s2p = mul2(fma2(meanp, meanp, d2p), kTwo);

        float ma, mb, da, db, sa, sb;
        upk2(meanp, ma, mb);
        upk2(d2p, da, db);
        upk2(s2p, sa, sb);
        __half2 ha, hb;
        {
            float disc = sqrtf(da);
            float am = fabsf(ma);
            float lam2v = fmaxf(copysignf(am + disc, ma), 1e-10f);
            float rb = __fdividef(fabsf(am - disc), lam2v);
            ha = __floats2half2_rn(__expf(-2.0f * rb * rb), sa);
        }
        {
            float disc = sqrtf(db);
            float am = fabsf(mb);
            float lam2v = fmaxf(copysignf(am + disc, mb), 1e-10f);
            float rb = __fdividef(fabsf(am - disc), lam2v);
            hb = __floats2half2_rn(__expf(-2.0f * rb * rb), sb);
        }
        *(uint2*)tsp = make_uint2(*(unsigned int*)&ha, *(unsigned int*)&hb);
        m = fmaxf(m, fmaxf(sa, sb));
        tsp += Wd;
        if (k < 7) {
#pragma unroll
            for (int d = 0; d < 4; d++) {
                w[d][0] = w[d + 1][0]; w[d][1] = w[d + 1][1]; w[d][2] = w[d + 1][2];
            }
#pragma unroll
            for (int c = 0; c < 3; c++)
                w[4][c] = s2p_base[(size_t)(r0 + k + 5) * SGT2 + cq + c];
        }
    }
    return m;
}

// Border path: fully scalar, per-pixel generic/interior selection (rare).
__device__ __forceinline__ float ts_border_run(const float* sg, __half2* tsp0,
                                               int txp, int r0, int i0, int j0) {
    float m = 0.0f;
#pragma unroll
    for (int c = 0; c < 2; c++) {
        int lj = 2 * txp + c + 2;
        int gj = j0 + 2 * txp + c;
        __half2* tsp = tsp0 + c;
        for (int k = 0; k < 8; k++) {
            int gi = i0 + r0 + k;
            int li = r0 + k + 2;
            float h00, h01, h11;
            if ((gj < 2) | (gj >= Wd - 2) | (gi < 2) | (gi >= Hd - 2)) {
                hess_g(sg, SGT, li, lj, gi, gj, h00, h01, h11);
            } else {
                const float* pc = sg + li * SGT + lj;
                h00 = 0.25f * (pc[2 * SGT] - 2.0f * pc[0] + pc[-2 * SGT]);
                h01 = 0.25f * ((pc[SGT + 1] - pc[-SGT + 1]) - (pc[SGT - 1] - pc[-SGT - 1]));
                h11 = 0.25f * (pc[-2] - 2.0f * pc[0] + pc[2]);
            }
            float mean = 0.5f * (h00 + h11);
            float diff = 0.5f * (h00 - h11);
            float d2 = diff * diff + h01 * h01;
            float s2 = 2.0f * (mean * mean + d2);
            m = fmaxf(m, eig_store(mean, d2, s2, tsp));
            tsp += Wd;
        }
    }
    return m;
}

// ---------------------------------------------------------------------------
// K1: grayscale + separable 5x5 blur + Hessian -> packed {t1, s2} + max(s^2).
// Tile 128x64, 512 threads, dynamic smem: sgray[72][136] then sg[68][132]
// overlay; shb[72][132].
// ---------------------------------------------------------------------------
__global__ void __launch_bounds__(512, 2) k_grayblur_ts(
        const float* __restrict__ x, const float* __restrict__ to_gray) {
    extern __shared__ __align__(16) float buf[];
    float* sgray = buf;              // [72][136]
    float* shb   = buf + 72 * SGS;   // [72][132]
    float* sg    = buf;              // [68][132] overlays sgray

    const int b  = blockIdx.z;
    const int i0 = blockIdx.y * 64;
    const int j0 = blockIdx.x * 128;
    const int t  = threadIdx.x;

    const float c0 = to_gray[0], c1 = to_gray[1], c2 = to_gray[2];
    const float* __restrict__ xr = x + (size_t)b * 3 * Hd * Wd;
    const float* __restrict__ xg = xr + (size_t)Hd * Wd;
    const float* __restrict__ xb = xg + (size_t)Hd * Wd;

    // Gray load: 72 rows x 34 float4-quads (halo 4). Interior blocks skip checks.
    const bool interior = (blockIdx.x > 0) & (blockIdx.x < gridDim.x - 1) &
                          (blockIdx.y > 0) & (blockIdx.y < gridDim.y - 1);
    if (interior) {
        for (int idx = t; idx < 72 * 34; idx += 512) {
            int li = idx / 34, q = idx - li * 34;
            size_t o = (size_t)(i0 + li - 4) * Wd + (j0 + q * 4 - 4);
            float4 r = *(const float4*)(xr + o);
            float4 g = *(const float4*)(xg + o);
            float4 bb = *(const float4*)(xb + o);
            float4 v;
            v.x = c0 * r.x + c1 * g.x + c2 * bb.x;
            v.y = c0 * r.y + c1 * g.y + c2 * bb.y;
            v.z = c0 * r.z + c1 * g.z + c2 * bb.z;
            v.w = c0 * r.w + c1 * g.w + c2 * bb.w;
            *(float4*)&sgray[li * SGS + q * 4] = v;
        }
    } else {
        for (int idx = t; idx < 72 * 34; idx += 512) {
            int li = idx / 34, q = idx - li * 34;
            int gi = i0 + li - 4, gjq = j0 + q * 4 - 4;
            float4 v = make_float4(0.f, 0.f, 0.f, 0.f);
            if ((unsigned)gi < Hd && (unsigned)gjq < Wd) {
                size_t o = (size_t)gi * Wd + gjq;
                float4 r = *(const float4*)(xr + o);
                float4 g = *(const float4*)(xg + o);
                float4 bb = *(const float4*)(xb + o);
                v.x = c0 * r.x + c1 * g.x + c2 * bb.x;
                v.y = c0 * r.y + c1 * g.y + c2 * bb.y;
                v.z = c0 * r.z + c1 * g.z + c2 * bb.z;
                v.w = c0 * r.w + c1 * g.w + c2 * bb.w;
            }
            *(float4*)&sgray[li * SGS + q * 4] = v;
        }
    }
    __syncthreads();

    // Horizontal 5-tap: 72 rows x 33 quads (out cols 0..131)
    for (int idx = t; idx < 72 * 33; idx += 512) {
        int li = idx / 33, q = idx - li * 33;
        const float* r = &sgray[li * SGS + q * 4];
        float4 A = *(const float4*)r;
        float4 B = *(const float4*)(r + 4);
        float4 o;
        o.x = W0 * (A.x + B.x) + W1 * (A.y + A.w) + W2 * A.z;
        o.y = W0 * (A.y + B.y) + W1 * (A.z + B.x) + W2 * A.w;
        o.z = W0 * (A.z + B.z) + W1 * (A.w + B.y) + W2 * B.x;
        o.w = W0 * (A.w + B.w) + W1 * (B.x + B.z) + W2 * B.y;
        *(float4*)&shb[li * SHS + q * 4] = o;
    }
    __syncthreads();

    // Vertical 5-tap: 17 row-quads x 132 cols -> sg (overlays dead sgray)
    for (int idx = t; idx < 17 * 132; idx += 512) {
        int rq = idx / 132, lj = idx - rq * 132;
        const float* p = &shb[rq * 4 * SHS + lj];
        float a0 = p[0], a1 = p[SHS], a2 = p[2 * SHS], a3 = p[3 * SHS];
        float a4 = p[4 * SHS], a5 = p[5 * SHS], a6 = p[6 * SHS], a7 = p[7 * SHS];
        float* o = &sg[rq * 4 * SGT + lj];
        o[0]       = W0 * (a0 + a4) + W1 * (a1 + a3) + W2 * a2;
        o[SGT]     = W0 * (a1 + a5) + W1 * (a2 + a4) + W2 * a3;
        o[2 * SGT] = W0 * (a2 + a6) + W1 * (a3 + a5) + W2 * a4;
        o[3 * SGT] = W0 * (a3 + a7) + W1 * (a4 + a6) + W2 * a5;
    }
    __syncthreads();

    // Hessian -> packed {t1, s2} + max(s2): thread owns col-pair txp, 8 rows.
    int txp = t & 63, ty = t >> 6;
    int r0 = ty * 8;
    int gj0 = j0 + 2 * txp;
    __half2* tsp = d_ts + ((size_t)b * Hd + (i0 + r0)) * Wd + gj0;
    bool jb = (gj0 < 2) | (gj0 + 1 >= Wd - 2);
    bool rowborder = (i0 == 0) | (i0 + 64 == Hd);
    float m;
    if (jb | rowborder)
        m = ts_border_run(sg, tsp, txp, r0, i0, j0);
    else
        m = ts_pair_run(sg, tsp, txp, r0);

#pragma unroll
    for (int o = 16; o > 0; o >>= 1)
        m = fmaxf(m, __shfl_xor_sync(0xffffffffu, m, o));
    __shared__ float wm[16];
    __shared__ int sflag;
    int lane = t & 31, wid = t >> 5;
    if (lane == 0) wm[wid] = m;
    __syncthreads();
    if (t == 0) {
        m = wm[0];
#pragma unroll
        for (int i = 1; i < 16; i++) m = fmaxf(m, wm[i]);
        d_blockmax[(b << 7) | (blockIdx.y << 3) | blockIdx.x] = m;
        __threadfence();
        unsigned int c = atomicAdd(&d_counter, 1u);
        sflag = (c == (unsigned)(Bd * 128 - 1));
    }
    __syncthreads();

    if (sflag) {  // last-finishing block computes gamma (self-reset counter)
        __shared__ float sbm[Bd];
        if (wid < Bd) {
            float m2 = 0.0f;
#pragma unroll
            for (int i = 0; i < 4; i++)
                m2 = fmaxf(m2, d_blockmax[(wid << 7) | (i * 32 + lane)]);
#pragma unroll
            for (int o = 16; o > 0; o >>= 1)
                m2 = fmaxf(m2, __shfl_xor_sync(0xffffffffu, m2, o));
            if (lane == 0) sbm[wid] = m2;
        }
        __syncthreads();
        if (t == 0) {
            float orall = 0.0f;
#pragma unroll
            for (int i = 0; i < Bd; i++) orall = fmaxf(orall, sbm[i]);
#pragma unroll
            for (int i = 0; i < Bd; i++) {
                float gm = (orall == 0.0f) ? 1.0f : 0.5f * sqrtf(sbm[i]);
                d_inv2g2[i] = 1.0f / (2.0f * gm * gm);
            }
            d_counter = 0;  // deterministic across graph replays
        }
    }
}

// ---------------------------------------------------------------------------
// K2: final elementwise response. 8 px/thread = 2 uint4 loads + 2 float4 stores.
// ---------------------------------------------------------------------------
__device__ __forceinline__ float fin1(float t1, float s2, float inv) {
    float vals = t1 * (1.0f - __expf(-s2 * inv));
    float f = fmaxf(0.0f, vals);
    return (f <= 0.0f) ? 1.0f : f;
}
__device__ __forceinline__ float4 fin4(uint4 raw, float inv) {
    float2 p0 = __half22float2(*reinterpret_cast<const __half2*>(&raw.x));
    float2 p1 = __half22float2(*reinterpret_cast<const __half2*>(&raw.y));
    float2 p2 = __half22float2(*reinterpret_cast<const __half2*>(&raw.z));
    float2 p3 = __half22float2(*reinterpret_cast<const __half2*>(&raw.w));
    float4 o;
    o.x = fin1(p0.x, p0.y, inv);
    o.y = fin1(p1.x, p1.y, inv);
    o.z = fin1(p2.x, p2.y, inv);
    o.w = fin1(p3.x, p3.y, inv);
    return o;
}

__global__ void __launch_bounds__(256) k_final(float* __restrict__ out) {
    const size_t i8 = (size_t)blockIdx.x * 256 + threadIdx.x;  // 8-px group
    const float inv = d_inv2g2[blockIdx.x >> 9];               // 512 blk/image

    const uint4* tp = (const uint4*)d_ts + i8 * 2;
    uint4 ra = tp[0];
    uint4 rb = tp[1];
    float4* op = (float4*)out + i8 * 2;
    op[0] = fin4(ra, inv);
    op[1] = fin4(rb, inv);
}

// ---------------------------------------------------------------------------
extern "C" void kernel_launch(void* const* d_in, const int* in_sizes, int n_in,
                              void* d_out, int out_size) {
    const float* x  = (const float*)d_in[0];
    const float* tg = (const float*)d_in[1];
    if (n_in >= 2 && in_sizes[0] == 3) {  // defensive: order per metadata
        const float* tmp = x; x = tg; tg = tmp;
    }
    float* out = (float*)d_out;

    const int smem = (72 * SGS + 72 * SHS) * 4;  // 77184 B
    cudaFuncSetAttribute(k_grayblur_ts,
                         cudaFuncAttributeMaxDynamicSharedMemorySize, smem);
    k_grayblur_ts<<<dim3(Wd / 128, Hd / 64, Bd), 512, smem>>>(x, tg);
    k_final<<<(Bd * Hd * Wd) / (256 * 8), 256>>>(out);
}